// round 2
// baseline (speedup 1.0000x reference)
#include <cuda_runtime.h>
#include <cuda_bf16.h>

#define VV 96
#define NPOLY 32
#define NPTS 32
#define PTS_PER_IMG (VV * VV)          // 9216
#define BATCH 4

// Scratch: combined mask per (b, y, x). 4*9216 floats = 147KB.
__device__ float g_comb[BATCH * PTS_PER_IMG];

// ---------------------------------------------------------------------------
// Kernel 1: polygon soft-mask + max over valid polygons.
// One warp per grid point, one lane per polygon.
// grid = (PTS_PER_IMG/8, BATCH), block = 256 (8 warps = 8 points).
// ---------------------------------------------------------------------------
__global__ void __launch_bounds__(256) mask_kernel(
    const float* __restrict__ polygons,      // [B][N][P][2]
    const float* __restrict__ validity)      // [B][N]
{
    const int b = blockIdx.y;

    // Padded shared arrays (stride 33) -> conflict-free LDS.128 / LDS.64
    __shared__ float4 sV[NPOLY][NPTS + 1];   // x0, y0, x1, y1
    __shared__ float2 sR[NPOLY][NPTS + 1];   // 1/(e^2+eps), 1/(dy+eps)
    __shared__ float  sval[NPOLY];

    const int tid = threadIdx.x;
    const float* pb = polygons + b * (NPOLY * NPTS * 2);

    // Precompute per-edge invariants (1024 edges, 4 per thread)
    for (int e = tid; e < NPOLY * NPTS; e += 256) {
        int n = e >> 5, p = e & 31;
        int p1 = (p + 1) & 31;
        float x0 = pb[(n * NPTS + p)  * 2 + 0];
        float y0 = pb[(n * NPTS + p)  * 2 + 1];
        float x1 = pb[(n * NPTS + p1) * 2 + 0];
        float y1 = pb[(n * NPTS + p1) * 2 + 1];
        float ex = x1 - x0, ey = y1 - y0;
        float esq = ex * ex + ey * ey + 1e-8f;
        sV[n][p] = make_float4(x0, y0, x1, y1);
        sR[n][p] = make_float2(__fdividef(1.0f, esq),
                               __fdividef(1.0f, ey + 1e-8f));
    }
    if (tid < NPOLY) sval[tid] = validity[b * NPOLY + tid];
    __syncthreads();

    const int w    = tid >> 5;              // warp -> point within block
    const int lane = tid & 31;              // lane -> polygon index
    const int pt   = blockIdx.x * 8 + w;    // 0 .. 9215

    const float px = (float)(pt % VV) * (1.0f / (VV - 1));
    const float py = (float)(pt / VV) * (1.0f / (VV - 1));

    float mind2 = 1e30f;
    int   par   = 0;

    #pragma unroll
    for (int p = 0; p < NPTS; p++) {
        float4 Vv = sV[lane][p];
        float2 R  = sR[lane][p];
        float ex = Vv.z - Vv.x;
        float ey = Vv.w - Vv.y;

        // closest-point-on-segment squared distance
        float vx = px - Vv.x;
        float vy = py - Vv.y;
        float t  = __saturatef((vx * ex + vy * ey) * R.x);
        float dx = vx - t * ex;
        float dy = vy - t * ey;
        float d2 = dx * dx + dy * dy;
        mind2 = fminf(mind2, d2);

        // ray crossing: (y0<=py) XOR (y1<=py), intersection to the right
        bool c0 = (Vv.y <= py);
        bool c1 = (Vv.w <= py);
        float ix = Vv.x + ex * ((py - Vv.y) * R.y);
        if ((c0 != c1) && (ix > px)) par ^= 1;
    }

    float d    = sqrtf(mind2);
    float sdf  = par ? -d : d;
    // sigmoid(-sdf * 100)
    float mask = __fdividef(1.0f, 1.0f + __expf(sdf * 100.0f));
    if (sval[lane] < 0.5f) mask = 0.0f;

    // warp max-reduce over polygons
    #pragma unroll
    for (int o = 16; o > 0; o >>= 1)
        mask = fmaxf(mask, __shfl_xor_sync(0xffffffffu, mask, o));

    if (lane == 0) g_comb[b * PTS_PER_IMG + pt] = mask;
}

// ---------------------------------------------------------------------------
// Kernel 2: extrude along depth with per-batch height cutoff. float4 writes.
// out[b][z][y][x] = comb[b][y][x] * (z < hv[b])
// ---------------------------------------------------------------------------
__global__ void __launch_bounds__(256) write_kernel(
    const float* __restrict__ attributes,    // [B][8]
    float* __restrict__ out)                 // [B][V][V][V]
{
    const int i = blockIdx.x * blockDim.x + threadIdx.x;   // float4 index
    // total float4s = 4*96*96*96/4 = 884736
    const int x4   = i % (VV / 4);
    int rest       = i / (VV / 4);
    const int y    = rest % VV;   rest /= VV;
    const int z    = rest % VV;
    const int b    = rest / VV;

    float a  = __saturatef(attributes[b * 8]);
    float hv = fminf(fmaxf(rintf(a * (float)VV), 1.0f), (float)VV);

    float4 c = *(const float4*)&g_comb[b * PTS_PER_IMG + y * VV + x4 * 4];
    if ((float)z >= hv) c = make_float4(0.f, 0.f, 0.f, 0.f);
    ((float4*)out)[i] = c;
}

// ---------------------------------------------------------------------------
extern "C" void kernel_launch(void* const* d_in, const int* in_sizes, int n_in,
                              void* d_out, int out_size) {
    const float* polygons   = (const float*)d_in[0];   // 4*32*32*2
    const float* attributes = (const float*)d_in[1];   // 4*8
    const float* validity   = (const float*)d_in[2];   // 4*32

    dim3 grid1(PTS_PER_IMG / 8, BATCH);
    mask_kernel<<<grid1, 256>>>(polygons, validity);

    const int n4 = out_size / 4;                       // 884736
    write_kernel<<<n4 / 256, 256>>>(attributes, (float*)d_out);
}

// round 3
// speedup vs baseline: 1.3171x; 1.3171x over previous
#include <cuda_runtime.h>
#include <math_constants.h>

#define VV 96
#define NPOLY 32
#define NPTS 32
#define BATCH 4
#define EPSF 1e-8f
#define THREADS 384   // 12 warps: 4 groups x 3 warps; group g handles polys [8g, 8g+8)

// Fused kernel: block = (y, b). Precompute per-(edge,y) linearized records in
// shared, evaluate 96 x-points (1 thread each, 4 polygon-groups in parallel),
// reduce, then extrude the row across all 96 z-slices.
__global__ void __launch_bounds__(THREADS, 2) fused_kernel(
    const float* __restrict__ polygons,    // [B][N][P][2]
    const float* __restrict__ attributes,  // [B][8]
    const float* __restrict__ validity,    // [B][N]
    float* __restrict__ out)               // [B][V][V][V]
{
    const int y = blockIdx.x;
    const int b = blockIdx.y;
    const float py = (float)y * (1.0f / 95.0f);

    __shared__ float4 rec1[NPOLY * NPTS];  // A, B, P, Q
    __shared__ float4 rec2[NPOLY * NPTS];  // F, G, ixm, -
    __shared__ float  skey[4][VV];
    __shared__ float  srow[VV];
    __shared__ float  sval[NPOLY];
    __shared__ float  shv;

    const int tid = threadIdx.x;
    const float* pb = polygons + b * (NPOLY * NPTS * 2);

    if (tid < NPOLY) sval[tid] = validity[b * NPOLY + tid];
    if (tid == 0) {
        float a = __saturatef(attributes[b * 8]);
        shv = fminf(fmaxf(rintf(a * (float)VV), 1.0f), (float)VV);
    }

    // ---- per-(edge, y) precompute: 1024 records ----
    for (int e = tid; e < NPOLY * NPTS; e += THREADS) {
        int n = e >> 5, p = e & 31, p1 = (p + 1) & 31;
        float x0 = pb[(n * NPTS + p)  * 2 + 0];
        float y0 = pb[(n * NPTS + p)  * 2 + 1];
        float x1 = pb[(n * NPTS + p1) * 2 + 0];
        float y1 = pb[(n * NPTS + p1) * 2 + 1];
        float ex = x1 - x0, ey = y1 - y0;
        float F  = ex * ex + ey * ey;        // |e|^2 (no eps)
        float e2 = F + EPSF;                 // |e|^2 + eps (ref divisor)
        float rx = __fdividef(1.0f, e2);
        float vy = py - y0;
        float A  = ex * rx;
        float B  = (vy * ey - x0 * ex) * rx;
        float P  = -2.0f * x0;
        float Q  = x0 * x0 + vy * vy;
        float G  = -2.0f * e2;
        bool yc = ((y0 <= py) && (y1 > py)) || ((y1 <= py) && (y0 > py));
        float ix = x0 + ex * ((py - y0) * __fdividef(1.0f, (y1 - y0 + EPSF)));
        float ixm = yc ? ix : -1e30f;        // NaN ix with yc true stays NaN -> compare false (matches ref)
        rec1[e] = make_float4(A, B, P, Q);
        rec2[e] = make_float4(F, G, ixm, 0.0f);
    }
    __syncthreads();

    // ---- hot loop: thread -> one x point, group -> 8 polygons ----
    const int warp = tid >> 5, lane = tid & 31;
    const int g  = warp / 3;                 // polygon group 0..3
    const int xw = warp - g * 3;             // x chunk 0..2
    const int x  = xw * 32 + lane;

    const float u  = (float)x * (1.0f / 95.0f);
    const float u2 = u * u;
    float keymin = CUDART_INF_F;

    #pragma unroll 1
    for (int n = g * 8; n < g * 8 + 8; n++) {
        float minr = CUDART_INF_F;
        int par = 0;
        #pragma unroll 8
        for (int p = 0; p < NPTS; p++) {
            float4 r1 = rec1[n * NPTS + p];  // broadcast LDS.128
            float4 r2 = rec2[n * NPTS + p];
            float s  = fmaf(r1.x, u, r1.y);            // unclamped t
            float t  = __saturatef(s);
            float q  = fmaf(r1.z, u, r1.w);            // (u-x0)^2 + vy^2 - u^2
            float h  = fmaf(r2.y, s, r2.x * t);        // F*t + G*s
            float d2 = fmaf(t, h, q);                  // d^2 - u^2 (exact rewrite)
            minr = fminf(minr, d2);
            if (r2.z > u) par ^= 1;                    // ray crossing
        }
        float mind2 = fmaxf(minr + u2, 0.0f);
        float key = par ? -mind2 : mind2;              // signed d^2, orders like sdf
        if (sval[n] < 0.5f) key = CUDART_INF_F;        // invalid -> never selected
        keymin = fminf(keymin, key);
    }
    skey[g][x] = keymin;
    __syncthreads();

    // ---- combine 4 groups, sqrt+sigmoid once per point ----
    if (tid < VV) {
        float k = fminf(fminf(skey[0][tid], skey[1][tid]),
                        fminf(skey[2][tid], skey[3][tid]));
        float d   = sqrtf(fabsf(k));
        float sdf = (k < 0.0f) ? -d : d;
        // sigmoid(-100*sdf); k==+inf (all invalid) -> mask 0, matches ref
        srow[tid] = __fdividef(1.0f, 1.0f + __expf(100.0f * sdf));
    }
    __syncthreads();

    // ---- extrude: write 96 z-slices of this (b, y) row ----
    const float hv = shv;
    const float4* row4 = (const float4*)srow;
    float4* out4 = (float4*)out;
    const int base = (b * VV) * VV * (VV / 4) + y * (VV / 4);
    #pragma unroll
    for (int k = 0; k < (VV * (VV / 4)) / THREADS; k++) {
        int idx = tid + k * THREADS;
        int z = idx / (VV / 4);
        int x4 = idx - z * (VV / 4);
        float4 c = row4[x4];
        if ((float)z >= hv) c = make_float4(0.f, 0.f, 0.f, 0.f);
        out4[base + z * VV * (VV / 4) + x4] = c;
    }
}

extern "C" void kernel_launch(void* const* d_in, const int* in_sizes, int n_in,
                              void* d_out, int out_size) {
    const float* polygons   = (const float*)d_in[0];
    const float* attributes = (const float*)d_in[1];
    const float* validity   = (const float*)d_in[2];

    dim3 grid(VV, BATCH);
    fused_kernel<<<grid, THREADS>>>(polygons, attributes, validity, (float*)d_out);
}

// round 5
// speedup vs baseline: 1.5283x; 1.1604x over previous
#include <cuda_runtime.h>
#include <math_constants.h>

#define VV 96
#define NPOLY 32
#define NPTS 32
#define BATCH 4
#define EPSF 1e-8f
#define THREADS 384   // 12 warps: 4 poly-groups x 3 warps (3*32 = 96 x-points)

// Fused kernel: block = (y, b). Per-(edge,y) linearized records in shared,
// 96 x-points evaluated (1 thread each, 4 polygon-groups in parallel),
// reduce, then extrude the row across all 96 z-slices.
// __launch_bounds__(384,3): 3 blocks/SM -> all 384 blocks in ONE wave.
__global__ void __launch_bounds__(THREADS, 3) fused_kernel(
    const float* __restrict__ polygons,    // [B][N][P][2]
    const float* __restrict__ attributes,  // [B][8]
    const float* __restrict__ validity,    // [B][N]
    float* __restrict__ out)               // [B][V][V][V]
{
    const int y = blockIdx.x;
    const int b = blockIdx.y;
    const float py = (float)y * (1.0f / 95.0f);

    __shared__ float4 rec1[NPOLY * NPTS];  // A, B, nex, ney
    __shared__ float4 rec2[NPOLY * NPTS];  // x0, vy, ixm, -
    __shared__ float  skey[4][VV];
    __shared__ float  srow[VV];
    __shared__ float  sval[NPOLY];
    __shared__ float  shv;

    const int tid = threadIdx.x;
    const float* pb = polygons + b * (NPOLY * NPTS * 2);

    if (tid < NPOLY) sval[tid] = validity[b * NPOLY + tid];
    if (tid == 0) {
        float a = __saturatef(attributes[b * 8]);
        shv = fminf(fmaxf(rintf(a * (float)VV), 1.0f), (float)VV);
    }

    // ---- per-(edge, y) precompute: 1024 records ----
    for (int e = tid; e < NPOLY * NPTS; e += THREADS) {
        int n = e >> 5, p = e & 31, p1 = (p + 1) & 31;
        float x0 = pb[(n * NPTS + p)  * 2 + 0];
        float y0 = pb[(n * NPTS + p)  * 2 + 1];
        float x1 = pb[(n * NPTS + p1) * 2 + 0];
        float y1 = pb[(n * NPTS + p1) * 2 + 1];
        float ex = x1 - x0, ey = y1 - y0;
        float e2 = ex * ex + ey * ey + EPSF;     // ref divisor
        float rx = __fdividef(1.0f, e2);
        float vy = py - y0;
        float A  = ex * rx;                      // t(u) = A*u + B
        float B  = (vy * ey - x0 * ex) * rx;
        bool yc = ((y0 <= py) && (y1 > py)) || ((y1 <= py) && (y0 > py));
        float ix = x0 + ex * ((py - y0) * __fdividef(1.0f, (y1 - y0 + EPSF)));
        float ixm = yc ? ix : -1e30f;            // sentinel: never counts
        rec1[e] = make_float4(A, B, -ex, -ey);
        rec2[e] = make_float4(x0, vy, ixm, 0.0f);
    }
    __syncthreads();

    // ---- hot loop: thread -> one x point, group -> 8 polygons ----
    const int warp = tid >> 5, lane = tid & 31;
    const int g  = warp >> 2 == 0 ? warp / 3 : warp / 3;  // (kept simple below)
    const int grp = warp / 3;                // polygon group 0..3
    const int xw  = warp - grp * 3;          // x chunk 0..2
    const int x   = xw * 32 + lane;

    const float u = (float)x * (1.0f / 95.0f);
    float keymin = CUDART_INF_F;

    #pragma unroll 1
    for (int n = grp * 8; n < grp * 8 + 8; n++) {
        float mind2 = CUDART_INF_F;
        unsigned acc = 0;                     // bit31 accumulates parity
        #pragma unroll
        for (int p = 0; p < NPTS; p++) {
            float4 r1 = rec1[n * NPTS + p];   // broadcast LDS.128
            float4 r2 = rec2[n * NPTS + p];
            float t  = __saturatef(fmaf(r1.x, u, r1.y));
            float vx = u - r2.x;
            float dx = fmaf(t, r1.z, vx);     // vx - t*ex
            float dy = fmaf(t, r1.w, r2.y);   // vy - t*ey
            float d2 = fmaf(dy, dy, dx * dx); // exact form (no cancellation)
            mind2 = fminf(mind2, d2);
            acc ^= __float_as_uint(u - r2.z); // sign bit = (ixm > u), strict
        }
        float key = (acc & 0x80000000u) ? -mind2 : mind2;  // signed d^2
        if (sval[n] < 0.5f) key = CUDART_INF_F;            // invalid polygon
        keymin = fminf(keymin, key);
    }
    skey[grp][x] = keymin;
    __syncthreads();

    // ---- combine 4 groups, sqrt+sigmoid once per point ----
    if (tid < VV) {
        float k = fminf(fminf(skey[0][tid], skey[1][tid]),
                        fminf(skey[2][tid], skey[3][tid]));
        float d   = sqrtf(fabsf(k));
        float sdf = (k < 0.0f) ? -d : d;
        // sigmoid(-100*sdf); k==+inf (all invalid) -> mask 0, matches ref
        srow[tid] = __fdividef(1.0f, 1.0f + __expf(100.0f * sdf));
    }
    __syncthreads();

    // ---- extrude: write 96 z-slices of this (b, y) row ----
    const float hv = shv;
    const float4* row4 = (const float4*)srow;
    float4* out4 = (float4*)out;
    const int base = (b * VV) * VV * (VV / 4) + y * (VV / 4);
    #pragma unroll
    for (int k = 0; k < (VV * (VV / 4)) / THREADS; k++) {
        int idx = tid + k * THREADS;
        int z = idx / (VV / 4);
        int x4 = idx - z * (VV / 4);
        float4 c = row4[x4];
        if ((float)z >= hv) c = make_float4(0.f, 0.f, 0.f, 0.f);
        out4[base + z * VV * (VV / 4) + x4] = c;
    }
    (void)g;
}

extern "C" void kernel_launch(void* const* d_in, const int* in_sizes, int n_in,
                              void* d_out, int out_size) {
    const float* polygons   = (const float*)d_in[0];
    const float* attributes = (const float*)d_in[1];
    const float* validity   = (const float*)d_in[2];

    dim3 grid(VV, BATCH);
    fused_kernel<<<grid, THREADS>>>(polygons, attributes, validity, (float*)d_out);
}

// round 7
// speedup vs baseline: 1.9786x; 1.2947x over previous
#include <cuda_runtime.h>
#include <math_constants.h>

#define VV 96
#define NPOLY 32
#define NPTS 32
#define BATCH 4
#define EPSF 1e-8f
#define THREADS 256   // 8 warps; warp w owns polys [4w, 4w+4), sweeps all 96 x

// Block = (y, b). Per-(edge,y) linearized records in shared; each warp
// evaluates its 4 polygons over all 96 x-points (3 per lane -> each record
// load is amortized over 3 evals and 3 independent FMA chains).
__global__ void __launch_bounds__(THREADS, 3) fused_kernel(
    const float* __restrict__ polygons,    // [B][N][P][2]
    const float* __restrict__ attributes,  // [B][8]
    const float* __restrict__ validity,    // [B][N]
    float* __restrict__ out)               // [B][V][V][V]
{
    const int y = blockIdx.x;
    const int b = blockIdx.y;
    const float py = (float)y * (1.0f / 95.0f);

    __shared__ float4 rec1[NPOLY * NPTS];  // A, B, -ex, -ey
    __shared__ float4 rec2[NPOLY * NPTS];  // x0, vy, ixm, -
    __shared__ float  skey[8][VV];         // per-warp partial keys
    __shared__ float  srow[VV];
    __shared__ float  sval[NPOLY];
    __shared__ float  shv;

    const int tid = threadIdx.x;
    const float* pb = polygons + b * (NPOLY * NPTS * 2);

    if (tid < NPOLY) sval[tid] = validity[b * NPOLY + tid];
    if (tid == 0) {
        float a = __saturatef(attributes[b * 8]);
        shv = fminf(fmaxf(rintf(a * (float)VV), 1.0f), (float)VV);
    }

    // ---- per-(edge, y) precompute: 1024 records ----
    for (int e = tid; e < NPOLY * NPTS; e += THREADS) {
        int n = e >> 5, p = e & 31, p1 = (p + 1) & 31;
        float x0 = pb[(n * NPTS + p)  * 2 + 0];
        float y0 = pb[(n * NPTS + p)  * 2 + 1];
        float x1 = pb[(n * NPTS + p1) * 2 + 0];
        float y1 = pb[(n * NPTS + p1) * 2 + 1];
        float ex = x1 - x0, ey = y1 - y0;
        float e2 = ex * ex + ey * ey + EPSF;     // ref divisor
        float rx = __fdividef(1.0f, e2);
        float vy = py - y0;
        float A  = ex * rx;                      // t(u) = A*u + B
        float B  = (vy * ey - x0 * ex) * rx;
        bool yc = ((y0 <= py) && (y1 > py)) || ((y1 <= py) && (y0 > py));
        float ix = x0 + ex * ((py - y0) * __fdividef(1.0f, (y1 - y0 + EPSF)));
        float ixm = yc ? ix : -1e30f;            // sentinel: never counts
        rec1[e] = make_float4(A, B, -ex, -ey);
        rec2[e] = make_float4(x0, vy, ixm, 0.0f);
    }
    __syncthreads();

    // ---- hot loop: warp -> 4 polygons, lane -> 3 x-points ----
    const int warp = tid >> 5, lane = tid & 31;
    const float u0 = (float)(lane     ) * (1.0f / 95.0f);
    const float u1 = (float)(lane + 32) * (1.0f / 95.0f);
    const float u2 = (float)(lane + 64) * (1.0f / 95.0f);

    float key0 = CUDART_INF_F, key1 = CUDART_INF_F, key2 = CUDART_INF_F;

    #pragma unroll 1
    for (int n = warp * 4; n < warp * 4 + 4; n++) {
        float m0 = CUDART_INF_F, m1 = CUDART_INF_F, m2 = CUDART_INF_F;
        unsigned a0 = 0, a1 = 0, a2 = 0;       // bit31 accumulates parity
        #pragma unroll
        for (int p = 0; p < NPTS; p++) {
            float4 r1 = rec1[n * NPTS + p];    // broadcast LDS.128
            float4 r2 = rec2[n * NPTS + p];    // amortized over 3 evals

            float t0 = __saturatef(fmaf(r1.x, u0, r1.y));
            float t1 = __saturatef(fmaf(r1.x, u1, r1.y));
            float t2 = __saturatef(fmaf(r1.x, u2, r1.y));

            float dx0 = fmaf(t0, r1.z, u0 - r2.x);
            float dx1 = fmaf(t1, r1.z, u1 - r2.x);
            float dx2 = fmaf(t2, r1.z, u2 - r2.x);

            float dy0 = fmaf(t0, r1.w, r2.y);
            float dy1 = fmaf(t1, r1.w, r2.y);
            float dy2 = fmaf(t2, r1.w, r2.y);

            m0 = fminf(m0, fmaf(dy0, dy0, dx0 * dx0));
            m1 = fminf(m1, fmaf(dy1, dy1, dx1 * dx1));
            m2 = fminf(m2, fmaf(dy2, dy2, dx2 * dx2));

            a0 ^= __float_as_uint(u0 - r2.z);  // sign bit = (ixm > u)
            a1 ^= __float_as_uint(u1 - r2.z);
            a2 ^= __float_as_uint(u2 - r2.z);
        }
        float k0 = (a0 & 0x80000000u) ? -m0 : m0;
        float k1 = (a1 & 0x80000000u) ? -m1 : m1;
        float k2 = (a2 & 0x80000000u) ? -m2 : m2;
        if (sval[n] < 0.5f) { k0 = CUDART_INF_F; k1 = CUDART_INF_F; k2 = CUDART_INF_F; }
        key0 = fminf(key0, k0);
        key1 = fminf(key1, k1);
        key2 = fminf(key2, k2);
    }
    skey[warp][lane     ] = key0;
    skey[warp][lane + 32] = key1;
    skey[warp][lane + 64] = key2;
    __syncthreads();

    // ---- combine 8 warps, sqrt+sigmoid once per point ----
    if (tid < VV) {
        float k = skey[0][tid];
        #pragma unroll
        for (int w = 1; w < 8; w++) k = fminf(k, skey[w][tid]);
        float d   = sqrtf(fabsf(k));
        float sdf = (k < 0.0f) ? -d : d;
        // sigmoid(-100*sdf); k==+inf (all invalid) -> mask 0, matches ref
        srow[tid] = __fdividef(1.0f, 1.0f + __expf(100.0f * sdf));
    }
    __syncthreads();

    // ---- extrude: write 96 z-slices of this (b, y) row ----
    const float hv = shv;
    const float4* row4 = (const float4*)srow;
    float4* out4 = (float4*)out;
    const int base = (b * VV) * VV * (VV / 4) + y * (VV / 4);
    #pragma unroll
    for (int k = 0; k < (VV * (VV / 4)) / THREADS; k++) {
        int idx = tid + k * THREADS;
        int z = idx / (VV / 4);
        int x4 = idx - z * (VV / 4);
        float4 c = row4[x4];
        if ((float)z >= hv) c = make_float4(0.f, 0.f, 0.f, 0.f);
        out4[base + z * VV * (VV / 4) + x4] = c;
    }
}

extern "C" void kernel_launch(void* const* d_in, const int* in_sizes, int n_in,
                              void* d_out, int out_size) {
    const float* polygons   = (const float*)d_in[0];
    const float* attributes = (const float*)d_in[1];
    const float* validity   = (const float*)d_in[2];

    dim3 grid(VV, BATCH);
    fused_kernel<<<grid, THREADS>>>(polygons, attributes, validity, (float*)d_out);
}

// round 8
// speedup vs baseline: 2.4315x; 1.2289x over previous
#include <cuda_runtime.h>
#include <math_constants.h>

#define VV 96
#define NPOLY 32
#define NPTS 32
#define BATCH 4
#define EPSF 1e-8f
#define THREADS 256   // 8 warps

// Block = (y, b). Valid polygons compacted via ballot; hot loop runs only on
// them. Tasks = 16-edge half-polygons (2*nv tasks over 8 warps) for balance;
// per-half partial = min d^2 with edge-crossing parity folded into sign bit;
// combine recovers parity (sign XOR) and magnitude (min of abs) exactly.
__global__ void __launch_bounds__(THREADS, 3) fused_kernel(
    const float* __restrict__ polygons,    // [B][N][P][2]
    const float* __restrict__ attributes,  // [B][8]
    const float* __restrict__ validity,    // [B][N]
    float* __restrict__ out)               // [B][V][V][V]
{
    const int y = blockIdx.x;
    const int b = blockIdx.y;
    const float py = (float)y * (1.0f / 95.0f);

    __shared__ float4 rec1[NPOLY * NPTS];  // A, B, -ex, -ey
    __shared__ float4 rec2[NPOLY * NPTS];  // x0, vy, ixm, 0
    __shared__ float  skey[32][VV];        // per-task partial keys (one round)
    __shared__ float  srow[VV];            // running key min -> final mask row
    __shared__ int    smap[NPOLY];
    __shared__ int    snv;
    __shared__ float  shv;

    const int tid = threadIdx.x;

    // ---- compact valid polygon indices (warp 0) ----
    if (tid < 32) {
        float v = validity[b * NPOLY + tid];
        unsigned mask = __ballot_sync(0xffffffffu, v >= 0.5f);
        if (v >= 0.5f) smap[__popc(mask & ((1u << tid) - 1u))] = tid;
        if (tid == 0) snv = __popc(mask);
    }
    if (tid == 32) {
        float a = __saturatef(attributes[b * 8]);
        shv = fminf(fmaxf(rintf(a * (float)VV), 1.0f), (float)VV);
    }
    if (tid < VV) srow[tid] = CUDART_INF_F;
    __syncthreads();

    const int nv = snv;
    const float* pb = polygons + b * (NPOLY * NPTS * 2);

    // ---- per-(valid edge, y) precompute ----
    for (int e = tid; e < nv * NPTS; e += THREADS) {
        int nc = e >> 5, p = e & 31, p1 = (p + 1) & 31;
        int n = smap[nc];
        float x0 = pb[(n * NPTS + p)  * 2 + 0];
        float y0 = pb[(n * NPTS + p)  * 2 + 1];
        float x1 = pb[(n * NPTS + p1) * 2 + 0];
        float y1 = pb[(n * NPTS + p1) * 2 + 1];
        float ex = x1 - x0, ey = y1 - y0;
        float e2 = ex * ex + ey * ey + EPSF;     // ref divisor
        float rx = __fdividef(1.0f, e2);
        float vy = py - y0;
        float A  = ex * rx;                      // t(u) = A*u + B
        float B  = (vy * ey - x0 * ex) * rx;
        bool yc = ((y0 <= py) && (y1 > py)) || ((y1 <= py) && (y0 > py));
        float ix = x0 + ex * ((py - y0) * __fdividef(1.0f, (y1 - y0 + EPSF)));
        float ixm = yc ? ix : -1e30f;            // sentinel: never counts
        rec1[e] = make_float4(A, B, -ex, -ey);
        rec2[e] = make_float4(x0, vy, ixm, 0.0f);
    }
    __syncthreads();

    const int warp = tid >> 5, lane = tid & 31;
    const float u0 = (float)(lane     ) * (1.0f / 95.0f);
    const float u1 = (float)(lane + 32) * (1.0f / 95.0f);
    const float u2 = (float)(lane + 64) * (1.0f / 95.0f);

    const int T = 2 * nv;                        // half-poly tasks
    for (int r = 0; r < 64; r += 32) {
        const int lim = min(T - r, 32);
        if (lim <= 0) break;                     // uniform across block

        #pragma unroll 1
        for (int t = warp; t < lim; t += 8) {
            const int g = r + t;
            const int base = (g >> 1) * NPTS + (g & 1) * 16;
            float m0 = CUDART_INF_F, m1 = CUDART_INF_F, m2 = CUDART_INF_F;
            unsigned a0 = 0, a1 = 0, a2 = 0;     // bit31 = parity
            #pragma unroll
            for (int p = 0; p < 16; p++) {
                float4 q1 = rec1[base + p];      // broadcast LDS.128
                float4 q2 = rec2[base + p];

                float t0 = __saturatef(fmaf(q1.x, u0, q1.y));
                float t1 = __saturatef(fmaf(q1.x, u1, q1.y));
                float t2 = __saturatef(fmaf(q1.x, u2, q1.y));

                float dx0 = fmaf(t0, q1.z, u0 - q2.x);
                float dx1 = fmaf(t1, q1.z, u1 - q2.x);
                float dx2 = fmaf(t2, q1.z, u2 - q2.x);

                float dy0 = fmaf(t0, q1.w, q2.y);
                float dy1 = fmaf(t1, q1.w, q2.y);
                float dy2 = fmaf(t2, q1.w, q2.y);

                m0 = fminf(m0, fmaf(dy0, dy0, dx0 * dx0));
                m1 = fminf(m1, fmaf(dy1, dy1, dx1 * dx1));
                m2 = fminf(m2, fmaf(dy2, dy2, dx2 * dx2));

                a0 ^= __float_as_uint(u0 - q2.z);  // sign = (ixm > u)
                a1 ^= __float_as_uint(u1 - q2.z);
                a2 ^= __float_as_uint(u2 - q2.z);
            }
            skey[t][lane     ] = __uint_as_float(__float_as_uint(m0) | (a0 & 0x80000000u));
            skey[t][lane + 32] = __uint_as_float(__float_as_uint(m1) | (a1 & 0x80000000u));
            skey[t][lane + 64] = __uint_as_float(__float_as_uint(m2) | (a2 & 0x80000000u));
        }
        __syncthreads();

        // combine halves -> per-poly key -> running min
        if (tid < VV) {
            float kmin = srow[tid];
            for (int i = 0; i < lim; i += 2) {
                unsigned b0 = __float_as_uint(skey[i    ][tid]);
                unsigned b1 = __float_as_uint(skey[i + 1][tid]);
                unsigned par = (b0 ^ b1) & 0x80000000u;
                float m = fminf(__uint_as_float(b0 & 0x7fffffffu),
                                __uint_as_float(b1 & 0x7fffffffu));
                kmin = fminf(kmin, __uint_as_float(__float_as_uint(m) | par));
            }
            srow[tid] = kmin;
        }
        __syncthreads();
    }

    // ---- sqrt + sigmoid once per point ----
    if (tid < VV) {
        float k = srow[tid];
        float d   = sqrtf(fabsf(k));
        float sdf = (__float_as_uint(k) & 0x80000000u) ? -d : d;
        // sigmoid(-100*sdf); k==+inf (no valid poly) -> mask 0, matches ref
        srow[tid] = __fdividef(1.0f, 1.0f + __expf(100.0f * sdf));
    }
    __syncthreads();

    // ---- extrude: write 96 z-slices of this (b, y) row ----
    const float hv = shv;
    const float4* row4 = (const float4*)srow;
    float4* out4 = (float4*)out;
    const int base = (b * VV) * VV * (VV / 4) + y * (VV / 4);
    #pragma unroll
    for (int k = 0; k < (VV * (VV / 4)) / THREADS; k++) {
        int idx = tid + k * THREADS;
        int z = idx / (VV / 4);
        int x4 = idx - z * (VV / 4);
        float4 c = row4[x4];
        if ((float)z >= hv) c = make_float4(0.f, 0.f, 0.f, 0.f);
        out4[base + z * VV * (VV / 4) + x4] = c;
    }
}

extern "C" void kernel_launch(void* const* d_in, const int* in_sizes, int n_in,
                              void* d_out, int out_size) {
    const float* polygons   = (const float*)d_in[0];
    const float* attributes = (const float*)d_in[1];
    const float* validity   = (const float*)d_in[2];

    dim3 grid(VV, BATCH);
    fused_kernel<<<grid, THREADS>>>(polygons, attributes, validity, (float*)d_out);
}

// round 9
// speedup vs baseline: 2.6944x; 1.1081x over previous
#include <cuda_runtime.h>
#include <math_constants.h>

#define VV 96
#define NPOLY 32
#define NPTS 32
#define BATCH 4
#define EPSF 1e-8f
#define THREADS 512   // 16 warps; warp w sweeps compacted polys w, w+16, ...

// Block = (y, b). Valid polygons compacted via ballot. Each warp evaluates
// whole polygons (parity + min-d^2 complete in registers -> signed key),
// 3 x-points per lane; one 16-way smem reduce; fused extrude.
__global__ void __launch_bounds__(THREADS, 2) fused_kernel(
    const float* __restrict__ polygons,    // [B][N][P][2]
    const float* __restrict__ attributes,  // [B][8]
    const float* __restrict__ validity,    // [B][N]
    float* __restrict__ out)               // [B][V][V][V]
{
    const int y = blockIdx.x;
    const int b = blockIdx.y;
    const float py = (float)y * (1.0f / 95.0f);

    __shared__ float4 rec1[NPOLY * NPTS];  // A, B, -ex, -ey
    __shared__ float4 rec2[NPOLY * NPTS];  // x0, vy, ixm, 0
    __shared__ float  skey[16][VV];        // per-warp partial keys
    __shared__ float  srow[VV];
    __shared__ int    smap[NPOLY];
    __shared__ int    snv;
    __shared__ float  shv;

    const int tid = threadIdx.x;

    // ---- compact valid polygon indices (warp 0) ----
    if (tid < 32) {
        float v = validity[b * NPOLY + tid];
        unsigned mask = __ballot_sync(0xffffffffu, v >= 0.5f);
        if (v >= 0.5f) smap[__popc(mask & ((1u << tid) - 1u))] = tid;
        if (tid == 0) snv = __popc(mask);
    }
    if (tid == 32) {
        float a = __saturatef(attributes[b * 8]);
        shv = fminf(fmaxf(rintf(a * (float)VV), 1.0f), (float)VV);
    }
    __syncthreads();

    const int nv = snv;
    const float* pb = polygons + b * (NPOLY * NPTS * 2);

    // ---- per-(valid edge, y) precompute ----
    for (int e = tid; e < nv * NPTS; e += THREADS) {
        int nc = e >> 5, p = e & 31, p1 = (p + 1) & 31;
        int n = smap[nc];
        float x0 = pb[(n * NPTS + p)  * 2 + 0];
        float y0 = pb[(n * NPTS + p)  * 2 + 1];
        float x1 = pb[(n * NPTS + p1) * 2 + 0];
        float y1 = pb[(n * NPTS + p1) * 2 + 1];
        float ex = x1 - x0, ey = y1 - y0;
        float e2 = ex * ex + ey * ey + EPSF;     // ref divisor
        float rx = __fdividef(1.0f, e2);
        float vy = py - y0;
        float A  = ex * rx;                      // t(u) = A*u + B
        float B  = (vy * ey - x0 * ex) * rx;
        bool yc = ((y0 <= py) && (y1 > py)) || ((y1 <= py) && (y0 > py));
        float ix = x0 + ex * ((py - y0) * __fdividef(1.0f, (y1 - y0 + EPSF)));
        float ixm = yc ? ix : -1e30f;            // sentinel: never counts
        rec1[e] = make_float4(A, B, -ex, -ey);
        rec2[e] = make_float4(x0, vy, ixm, 0.0f);
    }
    __syncthreads();

    const int warp = tid >> 5, lane = tid & 31;
    const float u0 = (float)(lane     ) * (1.0f / 95.0f);
    const float u1 = (float)(lane + 32) * (1.0f / 95.0f);
    const float u2 = (float)(lane + 64) * (1.0f / 95.0f);

    float key0 = CUDART_INF_F, key1 = CUDART_INF_F, key2 = CUDART_INF_F;

    #pragma unroll 1
    for (int n = warp; n < nv; n += 16) {
        float m0 = CUDART_INF_F, m1 = CUDART_INF_F, m2 = CUDART_INF_F;
        unsigned a0 = 0, a1 = 0, a2 = 0;       // bit31 accumulates parity
        #pragma unroll
        for (int p = 0; p < NPTS; p++) {
            float4 q1 = rec1[n * NPTS + p];    // broadcast LDS.128
            float4 q2 = rec2[n * NPTS + p];    // amortized over 3 evals

            float t0 = __saturatef(fmaf(q1.x, u0, q1.y));
            float t1 = __saturatef(fmaf(q1.x, u1, q1.y));
            float t2 = __saturatef(fmaf(q1.x, u2, q1.y));

            float dx0 = fmaf(t0, q1.z, u0 - q2.x);
            float dx1 = fmaf(t1, q1.z, u1 - q2.x);
            float dx2 = fmaf(t2, q1.z, u2 - q2.x);

            float dy0 = fmaf(t0, q1.w, q2.y);
            float dy1 = fmaf(t1, q1.w, q2.y);
            float dy2 = fmaf(t2, q1.w, q2.y);

            m0 = fminf(m0, fmaf(dy0, dy0, dx0 * dx0));
            m1 = fminf(m1, fmaf(dy1, dy1, dx1 * dx1));
            m2 = fminf(m2, fmaf(dy2, dy2, dx2 * dx2));

            a0 ^= __float_as_uint(u0 - q2.z);  // sign bit = (ixm > u)
            a1 ^= __float_as_uint(u1 - q2.z);
            a2 ^= __float_as_uint(u2 - q2.z);
        }
        float k0 = (a0 & 0x80000000u) ? -m0 : m0;   // signed d^2 key
        float k1 = (a1 & 0x80000000u) ? -m1 : m1;
        float k2 = (a2 & 0x80000000u) ? -m2 : m2;
        key0 = fminf(key0, k0);
        key1 = fminf(key1, k1);
        key2 = fminf(key2, k2);
    }
    skey[warp][lane     ] = key0;
    skey[warp][lane + 32] = key1;
    skey[warp][lane + 64] = key2;
    __syncthreads();

    // ---- combine 16 warps, sqrt + sigmoid once per point ----
    if (tid < VV) {
        float k = skey[0][tid];
        #pragma unroll
        for (int w = 1; w < 16; w++) k = fminf(k, skey[w][tid]);
        float d   = sqrtf(fabsf(k));
        float sdf = (k < 0.0f) ? -d : d;
        // sigmoid(-100*sdf); k==+inf (no valid poly) -> mask 0, matches ref
        srow[tid] = __fdividef(1.0f, 1.0f + __expf(100.0f * sdf));
    }
    __syncthreads();

    // ---- extrude: write 96 z-slices of this (b, y) row ----
    const float hv = shv;
    const float4* row4 = (const float4*)srow;
    float4* out4 = (float4*)out;
    const int base = (b * VV) * VV * (VV / 4) + y * (VV / 4);
    #pragma unroll
    for (int k = 0; k < 5; k++) {
        int idx = tid + k * THREADS;           // 2304 float4s total
        if (idx < VV * (VV / 4)) {
            int z = idx / (VV / 4);
            int x4 = idx - z * (VV / 4);
            float4 c = row4[x4];
            if ((float)z >= hv) c = make_float4(0.f, 0.f, 0.f, 0.f);
            out4[base + z * VV * (VV / 4) + x4] = c;
        }
    }
}

extern "C" void kernel_launch(void* const* d_in, const int* in_sizes, int n_in,
                              void* d_out, int out_size) {
    const float* polygons   = (const float*)d_in[0];
    const float* attributes = (const float*)d_in[1];
    const float* validity   = (const float*)d_in[2];

    dim3 grid(VV, BATCH);
    fused_kernel<<<grid, THREADS>>>(polygons, attributes, validity, (float*)d_out);
}

// round 10
// speedup vs baseline: 2.7931x; 1.0366x over previous
#include <cuda_runtime.h>
#include <math_constants.h>

#define VV 96
#define NPOLY 32
#define NPTS 32
#define BATCH 4
#define EPSF 1e-8f
#define THREADS 384   // 12 warps; 3 blocks/SM -> all 384 blocks in ONE wave

// Block = (y, b). Valid polygons compacted via ballot. Each warp evaluates
// whole polygons (parity + min-d^2 complete in registers -> signed key),
// 3 x-points per lane; one 12-way smem reduce; fused extrude.
__global__ void __launch_bounds__(THREADS, 3) fused_kernel(
    const float* __restrict__ polygons,    // [B][N][P][2]
    const float* __restrict__ attributes,  // [B][8]
    const float* __restrict__ validity,    // [B][N]
    float* __restrict__ out)               // [B][V][V][V]
{
    const int y = blockIdx.x;
    const int b = blockIdx.y;
    const float py = (float)y * (1.0f / 95.0f);

    __shared__ float4 rec1[NPOLY * NPTS];  // A, B, -ex, -ey
    __shared__ float4 rec2[NPOLY * NPTS];  // x0, vy, ixm, 0
    __shared__ float  skey[12][VV];        // per-warp partial keys
    __shared__ float  srow[VV];
    __shared__ int    smap[NPOLY];
    __shared__ int    snv;
    __shared__ float  shv;

    const int tid = threadIdx.x;

    // ---- compact valid polygon indices (warp 0) ----
    if (tid < 32) {
        float v = validity[b * NPOLY + tid];
        unsigned mask = __ballot_sync(0xffffffffu, v >= 0.5f);
        if (v >= 0.5f) smap[__popc(mask & ((1u << tid) - 1u))] = tid;
        if (tid == 0) snv = __popc(mask);
    }
    if (tid == 32) {
        float a = __saturatef(attributes[b * 8]);
        shv = fminf(fmaxf(rintf(a * (float)VV), 1.0f), (float)VV);
    }
    __syncthreads();

    const int nv = snv;
    const float* pb = polygons + b * (NPOLY * NPTS * 2);

    // ---- per-(valid edge, y) precompute ----
    for (int e = tid; e < nv * NPTS; e += THREADS) {
        int nc = e >> 5, p = e & 31, p1 = (p + 1) & 31;
        int n = smap[nc];
        float x0 = pb[(n * NPTS + p)  * 2 + 0];
        float y0 = pb[(n * NPTS + p)  * 2 + 1];
        float x1 = pb[(n * NPTS + p1) * 2 + 0];
        float y1 = pb[(n * NPTS + p1) * 2 + 1];
        float ex = x1 - x0, ey = y1 - y0;
        float e2 = ex * ex + ey * ey + EPSF;     // ref divisor
        float rx = __fdividef(1.0f, e2);
        float vy = py - y0;
        float A  = ex * rx;                      // t(u) = A*u + B
        float B  = (vy * ey - x0 * ex) * rx;
        bool yc = ((y0 <= py) && (y1 > py)) || ((y1 <= py) && (y0 > py));
        float ix = x0 + ex * ((py - y0) * __fdividef(1.0f, (y1 - y0 + EPSF)));
        float ixm = yc ? ix : -1e30f;            // sentinel: never counts
        rec1[e] = make_float4(A, B, -ex, -ey);
        rec2[e] = make_float4(x0, vy, ixm, 0.0f);
    }
    __syncthreads();

    const int warp = tid >> 5, lane = tid & 31;
    const float u0 = (float)(lane     ) * (1.0f / 95.0f);
    const float u1 = (float)(lane + 32) * (1.0f / 95.0f);
    const float u2 = (float)(lane + 64) * (1.0f / 95.0f);

    float key0 = CUDART_INF_F, key1 = CUDART_INF_F, key2 = CUDART_INF_F;

    #pragma unroll 1
    for (int n = warp; n < nv; n += 12) {
        float m0 = CUDART_INF_F, m1 = CUDART_INF_F, m2 = CUDART_INF_F;
        unsigned a0 = 0, a1 = 0, a2 = 0;       // bit31 accumulates parity
        #pragma unroll
        for (int p = 0; p < NPTS; p++) {
            float4 q1 = rec1[n * NPTS + p];    // broadcast LDS.128
            float4 q2 = rec2[n * NPTS + p];    // amortized over 3 evals

            float t0 = __saturatef(fmaf(q1.x, u0, q1.y));
            float t1 = __saturatef(fmaf(q1.x, u1, q1.y));
            float t2 = __saturatef(fmaf(q1.x, u2, q1.y));

            float dx0 = fmaf(t0, q1.z, u0 - q2.x);
            float dx1 = fmaf(t1, q1.z, u1 - q2.x);
            float dx2 = fmaf(t2, q1.z, u2 - q2.x);

            float dy0 = fmaf(t0, q1.w, q2.y);
            float dy1 = fmaf(t1, q1.w, q2.y);
            float dy2 = fmaf(t2, q1.w, q2.y);

            m0 = fminf(m0, fmaf(dy0, dy0, dx0 * dx0));
            m1 = fminf(m1, fmaf(dy1, dy1, dx1 * dx1));
            m2 = fminf(m2, fmaf(dy2, dy2, dx2 * dx2));

            a0 ^= __float_as_uint(u0 - q2.z);  // sign bit = (ixm > u)
            a1 ^= __float_as_uint(u1 - q2.z);
            a2 ^= __float_as_uint(u2 - q2.z);
        }
        float k0 = (a0 & 0x80000000u) ? -m0 : m0;   // signed d^2 key
        float k1 = (a1 & 0x80000000u) ? -m1 : m1;
        float k2 = (a2 & 0x80000000u) ? -m2 : m2;
        key0 = fminf(key0, k0);
        key1 = fminf(key1, k1);
        key2 = fminf(key2, k2);
    }
    skey[warp][lane     ] = key0;
    skey[warp][lane + 32] = key1;
    skey[warp][lane + 64] = key2;
    __syncthreads();

    // ---- combine 12 warps, sqrt + sigmoid once per point ----
    if (tid < VV) {
        float k = skey[0][tid];
        #pragma unroll
        for (int w = 1; w < 12; w++) k = fminf(k, skey[w][tid]);
        float d   = sqrtf(fabsf(k));
        float sdf = (k < 0.0f) ? -d : d;
        // sigmoid(-100*sdf); k==+inf (no valid poly) -> mask 0, matches ref
        srow[tid] = __fdividef(1.0f, 1.0f + __expf(100.0f * sdf));
    }
    __syncthreads();

    // ---- extrude: write 96 z-slices of this (b, y) row ----
    const float hv = shv;
    const float4* row4 = (const float4*)srow;
    float4* out4 = (float4*)out;
    const int base = (b * VV) * VV * (VV / 4) + y * (VV / 4);
    #pragma unroll
    for (int k = 0; k < 6; k++) {
        int idx = tid + k * THREADS;           // 2304 float4s total
        int z = idx / (VV / 4);
        int x4 = idx - z * (VV / 4);
        float4 c = row4[x4];
        if ((float)z >= hv) c = make_float4(0.f, 0.f, 0.f, 0.f);
        out4[base + z * VV * (VV / 4) + x4] = c;
    }
}

extern "C" void kernel_launch(void* const* d_in, const int* in_sizes, int n_in,
                              void* d_out, int out_size) {
    const float* polygons   = (const float*)d_in[0];
    const float* attributes = (const float*)d_in[1];
    const float* validity   = (const float*)d_in[2];

    dim3 grid(VV, BATCH);
    fused_kernel<<<grid, THREADS>>>(polygons, attributes, validity, (float*)d_out);
}